// round 3
// baseline (speedup 1.0000x reference)
#include <cuda_runtime.h>
#include <cstdint>

#define N_PTS 320
#define D_DIM 64
#define P_PERMS 1000

// Gram matrix of the original data: G[a][b] = <data[a], data[b]>  (409.6 KB, L2-resident)
__device__ float dG[N_PTS * N_PTS];

// ---------------------------------------------------------------------------
// Kernel 1: Gram matrix. One block per row a; thread t computes G[a][t].
// data is 80 KB -> L1/L2 resident; cost is negligible (~tens of us).
// ---------------------------------------------------------------------------
__global__ __launch_bounds__(N_PTS) void gram_kernel(const float* __restrict__ data) {
    __shared__ float4 xa[D_DIM / 4];
    int a = blockIdx.x;
    int t = threadIdx.x;
    if (t < D_DIM / 4) xa[t] = reinterpret_cast<const float4*>(data)[a * (D_DIM / 4) + t];
    __syncthreads();
    const float4* xb = reinterpret_cast<const float4*>(data) + t * (D_DIM / 4);
    float acc = 0.f;
#pragma unroll
    for (int k = 0; k < D_DIM / 4; ++k) {
        float4 u = xa[k];
        float4 v = __ldg(xb + k);
        acc = fmaf(u.x, v.x, acc);
        acc = fmaf(u.y, v.y, acc);
        acc = fmaf(u.z, v.z, acc);
        acc = fmaf(u.w, v.w, acc);
    }
    dG[a * N_PTS + t] = acc;
}

// ---------------------------------------------------------------------------
// Kernel 2: one block per permutation (block 0 = identity / original data).
// Thread t owns column t of the upper triangle: pairs (i, t), i < t.
// Per-position metadata for the thread's own column lives in registers;
// per-i metadata comes from one broadcast LDS.128 (sIC[i]).
//
//   sq(i,j) = nrm_i + nrm_j - 2 s_i s_j G[sigma_i, sigma_j]
//   val     = F(i,j) * sqrt(max(sq,0)),  F = max(fs_i, fs_j),
//             fs = fermion ? fa : bs   (exact for fa=-1, bs=1)
//   var     = (Sum w^2 - (Sum w)^2/M) / (M-1),  w = F*val  (fp64 finish)
// ---------------------------------------------------------------------------
__global__ __launch_bounds__(N_PTS) void qet_kernel(
    const float* __restrict__ faP, const float* __restrict__ bsP,
    const int* __restrict__ types, const int* __restrict__ perms,
    float* __restrict__ out)
{
    __shared__ uint4  sIC[N_PTS];        // {rowWordOff = sigma_i*320, -2*s_i, nrm_i, fs_i}
    __shared__ float2 sred[N_PTS / 32];

    const int p = blockIdx.x;
    const int t = threadIdx.x;

    const float fa = *faP;
    const float bs = *bsP;

    // sigma(t): identity for p==0, else perms row p-1
    const int pj = (p == 0) ? t : perms[(p - 1) * N_PTS + t];
    const int tt = types[t];
    const int tp = types[pj];

    float s;
    if (pj == t)                 s = 1.0f;
    else if (tt == 0 && tp == 0) s = fa;     // fermion-fermion factor
    else if (tt == 1 && tp == 1) s = bs;     // boson-boson factor
    else                         s = 1.0f;   // mixed

    const float nrmv = dG[pj * N_PTS + pj];            // ||data[sigma(t)]||^2
    const float fsv  = (tt == 0) ? fa : bs;            // position-type sign

    sIC[t] = make_uint4((unsigned)(pj * N_PTS),
                        __float_as_uint(-2.0f * s),
                        __float_as_uint(nrmv),
                        __float_as_uint(fsv));

    // thread-column registers
    const float* colp = dG + pj;     // gather base: G[. , sigma(t)]
    const float  sj   = s;
    const float  pnj  = nrmv;
    const float  fsj  = fsv;
    __syncthreads();

    float accv = 0.f;   // sum of w = F*val
    float accd = 0.f;   // sum of w^2
#pragma unroll 4
    for (int i = 0; i < t; ++i) {
        uint4 ic = sIC[i];                       // broadcast LDS.128
        float g  = __ldg(colp + ic.x);           // G[sigma_i, sigma_t] (L2/L1 gather)
        float sg = sj * g;
        float ns = pnj + __uint_as_float(ic.z);
        float d2 = fmaf(__uint_as_float(ic.y), sg, ns);
        d2 = fmaxf(d2, 0.0f);
        float v;
        asm("sqrt.approx.f32 %0, %1;" : "=f"(v) : "f"(d2));   // one MUFU.SQRT
        float fm = fmaxf(fsj, __uint_as_float(ic.w));          // F(i,t)
        float w  = fm * v;
        accv += w;
        accd  = fmaf(w, w, accd);
    }

    // block reduction (10 warps)
#pragma unroll
    for (int o = 16; o; o >>= 1) {
        accv += __shfl_down_sync(0xffffffffu, accv, o);
        accd += __shfl_down_sync(0xffffffffu, accd, o);
    }
    if ((t & 31) == 0) sred[t >> 5] = make_float2(accv, accd);
    __syncthreads();
    if (t == 0) {
        double Sv = 0.0, Sd = 0.0;
#pragma unroll
        for (int w2 = 0; w2 < N_PTS / 32; ++w2) { Sv += sred[w2].x; Sd += sred[w2].y; }
        const double M = (double)(N_PTS * (N_PTS - 1) / 2);   // 51040
        out[p] = (float)((Sd - Sv * Sv / M) / (M - 1.0));
    }
}

// ---------------------------------------------------------------------------
// inputs (metadata order): data[320*64] f32, fermion_antisymmetry f32[1],
// boson_symmetry f32[1], particle_types i32[320], perms i32[1000*320]
// output: stats f32[1001]
// ---------------------------------------------------------------------------
extern "C" void kernel_launch(void* const* d_in, const int* in_sizes, int n_in,
                              void* d_out, int out_size) {
    const float* data  = (const float*)d_in[0];
    const float* fa    = (const float*)d_in[1];
    const float* bs    = (const float*)d_in[2];
    const int*   types = (const int*)d_in[3];
    const int*   perms = (const int*)d_in[4];
    float*       out   = (float*)d_out;

    gram_kernel<<<N_PTS, N_PTS>>>(data);
    qet_kernel<<<P_PERMS + 1, N_PTS>>>(fa, bs, types, perms, out);
}

// round 4
// speedup vs baseline: 1.8768x; 1.8768x over previous
#include <cuda_runtime.h>
#include <cstdint>

#define N_PTS 320
#define D_DIM 64
#define P_PERMS 1000
#define NWARP (N_PTS / 32)

// Gram matrix of the ORIGINAL data: G[a][b] = <data[a], data[b]> (409.6 KB, L2-resident)
__device__ float dG[N_PTS * N_PTS];

// ---------------------------------------------------------------------------
// Kernel 1: Gram matrix. One block per row a; thread t computes G[a][t].
// ---------------------------------------------------------------------------
__global__ __launch_bounds__(N_PTS) void gram_kernel(const float* __restrict__ data) {
    __shared__ float4 xa[D_DIM / 4];
    int a = blockIdx.x;
    int t = threadIdx.x;
    if (t < D_DIM / 4) xa[t] = reinterpret_cast<const float4*>(data)[a * (D_DIM / 4) + t];
    __syncthreads();
    const float4* xb = reinterpret_cast<const float4*>(data) + t * (D_DIM / 4);
    float acc = 0.f;
#pragma unroll
    for (int k = 0; k < D_DIM / 4; ++k) {
        float4 u = xa[k];
        float4 v = __ldg(xb + k);
        acc = fmaf(u.x, v.x, acc);
        acc = fmaf(u.y, v.y, acc);
        acc = fmaf(u.z, v.z, acc);
        acc = fmaf(u.w, v.w, acc);
    }
    dG[a * N_PTS + t] = acc;
}

// ---------------------------------------------------------------------------
// Kernel 2: one block per permutation (block 0 = identity / original data).
//
// Key idea: sigma is a bijection, so summing over pairs (i,j) in permuted
// space == summing over pairs (a,b) = (sigma_i, sigma_j) in ORIGINAL space:
//   sq(a,b) = nrm_a + nrm_b - 2 * sInv[a]*sInv[b] * G[a,b]
//   F(a,b)  = max(fsInv[a], fsInv[b])          (exact for fa=-1, bs=+1)
// where sInv/fsInv are sign/type metadata scattered through sigma^{-1}.
// Thread t owns a NATURAL column b -> warp LDGs are fully coalesced
// (1 cache line / warp instruction instead of ~25 random sectors).
//
// Column-group ownership rotates by blockIdx so the heavy triangular warps
// don't all land on the same SM sub-partitions across resident blocks.
// ---------------------------------------------------------------------------
__global__ __launch_bounds__(N_PTS) void qet_kernel(
    const float* __restrict__ faP, const float* __restrict__ bsP,
    const int* __restrict__ types, const int* __restrict__ perms,
    float* __restrict__ out)
{
    __shared__ float4 meta[N_PTS];       // meta[a] = {sInv[a], fsInv[a], nrm_a, pad}
    __shared__ float2 sred[NWARP];

    const int p = blockIdx.x;
    const int t = threadIdx.x;

    const float fa = *faP;
    const float bs = *bsP;

    // sigma(t): identity for p==0, else perms row p-1
    const int pj = (p == 0) ? t : perms[(p - 1) * N_PTS + t];
    const int tt = types[t];
    const int tp = types[pj];

    float s;
    if (pj == t)                 s = 1.0f;
    else if (tt == 0 && tp == 0) s = fa;     // fermion-fermion swap factor
    else if (tt == 1 && tp == 1) s = bs;     // boson-boson swap factor
    else                         s = 1.0f;   // mixed

    const float fsv = (tt == 0) ? fa : bs;   // position-type sign of position t

    // Scatter through sigma^{-1}: original index a = pj gets position-t signs.
    meta[pj].x = s;                          // sInv[pj]
    meta[pj].y = fsv;                        // fsInv[pj]
    meta[t].z  = dG[t * (N_PTS + 1)];        // nrm_t (natural index, sign-free)
    __syncthreads();

    // This thread's column (rotated group assignment for SMSP balance)
    const int wid = t >> 5, lane = t & 31;
    const int cb = (((wid + p) % NWARP) << 5) + lane;

    const float4 mc  = meta[cb];
    const float  m2  = -2.0f * mc.x;         // -2 * sInv[cb]
    const float  pn  = mc.z;                 // nrm_cb
    const float  fcl = mc.y;                 // fsInv[cb]
    const float* gcol = dG + cb;             // coalesced: G[a*320 + cb]

    float accv = 0.f;   // sum of F*val
    float accd = 0.f;   // sum of val^2  (F^2 == 1)
#pragma unroll 8
    for (int a = 0; a < cb; ++a) {
        float4 ma = meta[a];                 // broadcast LDS.128
        float g   = __ldg(gcol + a * N_PTS); // coalesced LDG (1 line / warp)
        float sg  = ma.x * g;                // sInv[a] * G
        float ns  = pn + ma.z;               // nrm_cb + nrm_a
        float d2  = fmaf(m2, sg, ns);
        d2 = fmaxf(d2, 0.0f);
        float v;
        asm("sqrt.approx.f32 %0, %1;" : "=f"(v) : "f"(d2));
        float fm = fmaxf(fcl, ma.y);         // F(a, cb)
        accv = fmaf(fm, v, accv);
        accd = fmaf(v, v, accd);
    }

    // block reduction (10 warps)
#pragma unroll
    for (int o = 16; o; o >>= 1) {
        accv += __shfl_down_sync(0xffffffffu, accv, o);
        accd += __shfl_down_sync(0xffffffffu, accd, o);
    }
    if (lane == 0) sred[wid] = make_float2(accv, accd);
    __syncthreads();
    if (t == 0) {
        double Sv = 0.0, Sd = 0.0;
#pragma unroll
        for (int w2 = 0; w2 < NWARP; ++w2) { Sv += sred[w2].x; Sd += sred[w2].y; }
        const double M = (double)(N_PTS * (N_PTS - 1) / 2);   // 51040
        out[p] = (float)((Sd - Sv * Sv / M) / (M - 1.0));
    }
}

// ---------------------------------------------------------------------------
// inputs (metadata order): data[320*64] f32, fermion_antisymmetry f32[1],
// boson_symmetry f32[1], particle_types i32[320], perms i32[1000*320]
// output: stats f32[1001]
// ---------------------------------------------------------------------------
extern "C" void kernel_launch(void* const* d_in, const int* in_sizes, int n_in,
                              void* d_out, int out_size) {
    const float* data  = (const float*)d_in[0];
    const float* fa    = (const float*)d_in[1];
    const float* bs    = (const float*)d_in[2];
    const int*   types = (const int*)d_in[3];
    const int*   perms = (const int*)d_in[4];
    float*       out   = (float*)d_out;

    gram_kernel<<<N_PTS, N_PTS>>>(data);
    qet_kernel<<<P_PERMS + 1, N_PTS>>>(fa, bs, types, perms, out);
}